// round 1
// baseline (speedup 1.0000x reference)
#include <cuda_runtime.h>
#include <math.h>

#define NV   100000
#define NE   10000
#define NP   1600000
#define CIN  256
#define CMID 128
#define COUT 64
#define NEG  0.2f

// ---------------- scratch (device globals; no allocation allowed) ----------
__device__ float g_h[NV * COUT];        // MLP output h
__device__ float g_esum[NE * COUT];     // hyperedge accumulator
__device__ float g_ecnt[NE];            // hyperedge degree
__device__ float g_efeat[NE * COUT];    // hyperedge mean feature
__device__ float g_hgsum[NV * COUT];    // e2v accumulator
__device__ float g_gsum[NV * COUT];     // graph accumulator
__device__ float g_vcnt_hg[NV];         // vertex incidence degree
__device__ float g_vcnt_g[NV];          // vertex graph in-degree

__device__ __forceinline__ float lrelu(float v) { return v > 0.f ? v : NEG * v; }

// ---------------- zero accumulators ----------------------------------------
__global__ void zero_kernel() {
    int stride = gridDim.x * blockDim.x;
    for (int i = blockIdx.x * blockDim.x + threadIdx.x; i < NV * COUT; i += stride) {
        g_hgsum[i] = 0.f;
        g_gsum[i]  = 0.f;
        if (i < NE * COUT) g_esum[i] = 0.f;
        if (i < NE)        g_ecnt[i] = 0.f;
        if (i < NV) { g_vcnt_hg[i] = 0.f; g_vcnt_g[i] = 0.f; }
    }
}

// ---------------- fused MLP: h = lrelu(x@W1+b1)@W2 + b2 --------------------
// Block: 256 threads (8 warps), 32-row tile, 4 rows per warp.
// smem: W1 (128KB) + W2 (32KB) + biases + x tile (32KB) + mid tile (16KB)
#define TILE_R 32
#define RPW    4
#define MLP_THREADS 256
#define SMEM_FLOATS (CIN*CMID + CMID*COUT + CMID + COUT + TILE_R*CIN + TILE_R*CMID)

__global__ __launch_bounds__(MLP_THREADS, 1)
void mlp_kernel(const float* __restrict__ x,
                const float* __restrict__ W1, const float* __restrict__ b1,
                const float* __restrict__ W2, const float* __restrict__ b2) {
    extern __shared__ float sm[];
    float* W1s  = sm;                       // [256][128]
    float* W2s  = W1s + CIN * CMID;         // [128][64]
    float* b1s  = W2s + CMID * COUT;        // [128]
    float* b2s  = b1s + CMID;               // [64]
    float* xs   = b2s + COUT;               // [32][256]
    float* mids = xs + TILE_R * CIN;        // [32][128]

    int tid = threadIdx.x;
    for (int i = tid; i < CIN * CMID / 4; i += MLP_THREADS)
        ((float4*)W1s)[i] = ((const float4*)W1)[i];
    for (int i = tid; i < CMID * COUT / 4; i += MLP_THREADS)
        ((float4*)W2s)[i] = ((const float4*)W2)[i];
    if (tid < CMID) b1s[tid] = b1[tid];
    if (tid < COUT) b2s[tid] = b2[tid];

    int warp = tid >> 5, lane = tid & 31;
    int ntiles = NV / TILE_R;   // 3125, exact

    for (int tile = blockIdx.x; tile < ntiles; tile += gridDim.x) {
        __syncthreads();
        int row0 = tile * TILE_R;
        // stage x tile
        for (int i = tid; i < TILE_R * CIN / 4; i += MLP_THREADS)
            ((float4*)xs)[i] = ((const float4*)(x + (size_t)row0 * CIN))[i];
        __syncthreads();

        // ---- GEMM1: mid[r][j], lane owns j = 4*lane..4*lane+3
        float acc[RPW][4];
#pragma unroll
        for (int r = 0; r < RPW; r++)
#pragma unroll
            for (int q = 0; q < 4; q++) acc[r][q] = 0.f;

        const float* xrow = xs + (warp * RPW) * CIN;
        for (int k = 0; k < CIN; k += 4) {
            float4 xv[RPW];
#pragma unroll
            for (int r = 0; r < RPW; r++)
                xv[r] = *(const float4*)(xrow + r * CIN + k);
#pragma unroll
            for (int kk = 0; kk < 4; kk++) {
                float4 wv = *(const float4*)(W1s + (k + kk) * CMID + lane * 4);
#pragma unroll
                for (int r = 0; r < RPW; r++) {
                    float xr = (kk == 0) ? xv[r].x : (kk == 1) ? xv[r].y
                             : (kk == 2) ? xv[r].z : xv[r].w;
                    acc[r][0] += xr * wv.x;
                    acc[r][1] += xr * wv.y;
                    acc[r][2] += xr * wv.z;
                    acc[r][3] += xr * wv.w;
                }
            }
        }
        // bias + leaky relu -> mids (per-warp private region)
        {
            float4 bv = *(const float4*)(b1s + lane * 4);
#pragma unroll
            for (int r = 0; r < RPW; r++) {
                float4 m;
                m.x = lrelu(acc[r][0] + bv.x);
                m.y = lrelu(acc[r][1] + bv.y);
                m.z = lrelu(acc[r][2] + bv.z);
                m.w = lrelu(acc[r][3] + bv.w);
                *(float4*)(mids + (warp * RPW + r) * CMID + lane * 4) = m;
            }
        }
        __syncwarp();

        // ---- GEMM2: out[r][c], lane owns c = 2*lane, 2*lane+1
        float acc2[RPW][2];
#pragma unroll
        for (int r = 0; r < RPW; r++) { acc2[r][0] = 0.f; acc2[r][1] = 0.f; }

        const float* mrow = mids + (warp * RPW) * CMID;
        for (int k = 0; k < CMID; k += 4) {
            float4 mv[RPW];
#pragma unroll
            for (int r = 0; r < RPW; r++)
                mv[r] = *(const float4*)(mrow + r * CMID + k);
#pragma unroll
            for (int kk = 0; kk < 4; kk++) {
                float2 wv = *(const float2*)(W2s + (k + kk) * COUT + lane * 2);
#pragma unroll
                for (int r = 0; r < RPW; r++) {
                    float mr = (kk == 0) ? mv[r].x : (kk == 1) ? mv[r].y
                             : (kk == 2) ? mv[r].z : mv[r].w;
                    acc2[r][0] += mr * wv.x;
                    acc2[r][1] += mr * wv.y;
                }
            }
        }
        {
            float2 b2v = *(const float2*)(b2s + lane * 2);
#pragma unroll
            for (int r = 0; r < RPW; r++) {
                float2 o;
                o.x = acc2[r][0] + b2v.x;
                o.y = acc2[r][1] + b2v.y;
                *(float2*)(g_h + (size_t)(row0 + warp * RPW + r) * COUT + lane * 2) = o;
            }
        }
    }
}

// ---------------- scatter-add (mean numerator + count) ---------------------
// 16 threads per pair, float4 per thread, vector reduction atomics.
__global__ void scatter_kernel(const float* __restrict__ feat,
                               const int* __restrict__ sidx,
                               const int* __restrict__ didx,
                               float* __restrict__ sum,
                               float* __restrict__ cnt,
                               int npairs) {
    int t = blockIdx.x * blockDim.x + threadIdx.x;
    int i = t >> 4;
    if (i >= npairs) return;
    int l = t & 15;
    int s = __ldg(sidx + i);
    int d = __ldg(didx + i);
    float4 v = *(const float4*)(feat + (size_t)s * COUT + l * 4);
    float* dst = sum + (size_t)d * COUT + l * 4;
    asm volatile("red.global.add.v4.f32 [%0], {%1,%2,%3,%4};"
                 :: "l"(dst), "f"(v.x), "f"(v.y), "f"(v.z), "f"(v.w)
                 : "memory");
    if (l == 0) atomicAdd(cnt + d, 1.0f);
}

// ---------------- e_feat = e_sum / max(cnt,1) -------------------------------
__global__ void efeat_kernel() {
    int i = blockIdx.x * blockDim.x + threadIdx.x;
    if (i >= NE * COUT) return;
    float c = g_ecnt[i >> 6];
    g_efeat[i] = g_esum[i] / fmaxf(c, 1.0f);
}

// ---------------- final fuse + activation ----------------------------------
__global__ void final_kernel(const float* __restrict__ w, float* __restrict__ out) {
    int t = blockIdx.x * blockDim.x + threadIdx.x;
    if (t >= NV * COUT / 4) return;
    int v = t >> 4;
    float e0 = expf(w[0]), e1 = expf(w[1]);
    float sw0 = e0 / (e0 + e1), sw1 = e1 / (e0 + e1);
    float ih = 1.0f / fmaxf(g_vcnt_hg[v], 1.0f);
    float ig = 1.0f / fmaxf(g_vcnt_g[v], 1.0f);
    float4 hg = ((const float4*)g_hgsum)[t];
    float4 gg = ((const float4*)g_gsum)[t];
    float4 h  = ((const float4*)g_h)[t];
    float4 o;
    o.x = lrelu(sw0 * 0.5f * (gg.x * ig + hg.x * ih) + sw1 * h.x);
    o.y = lrelu(sw0 * 0.5f * (gg.y * ig + hg.y * ih) + sw1 * h.y);
    o.z = lrelu(sw0 * 0.5f * (gg.z * ig + hg.z * ih) + sw1 * h.z);
    o.w = lrelu(sw0 * 0.5f * (gg.w * ig + hg.w * ih) + sw1 * h.w);
    ((float4*)out)[t] = o;
}

// ---------------- launch ----------------------------------------------------
extern "C" void kernel_launch(void* const* d_in, const int* in_sizes, int n_in,
                              void* d_out, int out_size) {
    const float* x    = (const float*)d_in[0];
    const float* W1   = (const float*)d_in[1];
    const float* b1   = (const float*)d_in[2];
    const float* W2   = (const float*)d_in[3];
    const float* b2   = (const float*)d_in[4];
    const float* w    = (const float*)d_in[5];
    const int*   hg_v = (const int*)d_in[6];
    const int*   hg_e = (const int*)d_in[7];
    const int*   g_src= (const int*)d_in[8];
    const int*   g_dst= (const int*)d_in[9];
    float* out = (float*)d_out;

    float *p_h, *p_esum, *p_ecnt, *p_efeat, *p_hgsum, *p_gsum, *p_vch, *p_vcg;
    cudaGetSymbolAddress((void**)&p_h,     g_h);
    cudaGetSymbolAddress((void**)&p_esum,  g_esum);
    cudaGetSymbolAddress((void**)&p_ecnt,  g_ecnt);
    cudaGetSymbolAddress((void**)&p_efeat, g_efeat);
    cudaGetSymbolAddress((void**)&p_hgsum, g_hgsum);
    cudaGetSymbolAddress((void**)&p_gsum,  g_gsum);
    cudaGetSymbolAddress((void**)&p_vch,   g_vcnt_hg);
    cudaGetSymbolAddress((void**)&p_vcg,   g_vcnt_g);

    const size_t smem_bytes = (size_t)SMEM_FLOATS * sizeof(float); // ~209KB
    cudaFuncSetAttribute(mlp_kernel, cudaFuncAttributeMaxDynamicSharedMemorySize,
                         (int)smem_bytes);

    zero_kernel<<<4096, 256>>>();
    mlp_kernel<<<148, MLP_THREADS, smem_bytes>>>(x, W1, b1, W2, b2);

    int sc_blocks = (NP * 16 + 255) / 256;
    // v2e: mean of h over incidence pairs grouped by hyperedge
    scatter_kernel<<<sc_blocks, 256>>>(p_h, hg_v, hg_e, p_esum, p_ecnt, NP);
    efeat_kernel<<<(NE * COUT + 255) / 256, 256>>>();
    // e2v: mean of e_feat over incidence pairs grouped by vertex
    scatter_kernel<<<sc_blocks, 256>>>(p_efeat, hg_e, hg_v, p_hgsum, p_vch, NP);
    // graph: mean of h over edges grouped by destination vertex
    scatter_kernel<<<sc_blocks, 256>>>(p_h, g_src, g_dst, p_gsum, p_vcg, NP);

    final_kernel<<<(NV * COUT / 4 + 255) / 256, 256>>>(w, out);
}

// round 2
// speedup vs baseline: 1.0502x; 1.0502x over previous
#include <cuda_runtime.h>
#include <math.h>

#define NV   100000
#define NE   10000
#define NP   1600000
#define CIN  256
#define CMID 128
#define COUT 64
#define NEG  0.2f

// ---------------- scratch (device globals; no allocation allowed) ----------
__device__ float g_h[NV * COUT];        // MLP output h
__device__ float g_esum[NE * COUT];     // hyperedge accumulator
__device__ float g_ecnt[NE];            // hyperedge degree
__device__ float g_efeat[NE * COUT];    // hyperedge mean feature
__device__ float g_hgsum[NV * COUT];    // e2v accumulator
__device__ float g_gsum[NV * COUT];     // graph accumulator
__device__ float g_vcnt_hg[NV];         // vertex incidence degree
__device__ float g_vcnt_g[NV];          // vertex graph in-degree

__device__ __forceinline__ float lrelu(float v) { return v > 0.f ? v : NEG * v; }

typedef unsigned long long u64;

__device__ __forceinline__ u64 fma2(u64 a, u64 b, u64 c) {
    u64 d;
    asm("fma.rn.f32x2 %0, %1, %2, %3;" : "=l"(d) : "l"(a), "l"(b), "l"(c));
    return d;
}
__device__ __forceinline__ float sum2(u64 p) {
    float lo, hi;
    asm("mov.b64 {%0,%1}, %2;" : "=f"(lo), "=f"(hi) : "l"(p));
    return lo + hi;
}

// ---------------- zero accumulators ----------------------------------------
__global__ void zero_kernel() {
    int stride = gridDim.x * blockDim.x;
    float4 z = make_float4(0.f, 0.f, 0.f, 0.f);
    for (int i = blockIdx.x * blockDim.x + threadIdx.x; i < NV * COUT / 4; i += stride) {
        ((float4*)g_hgsum)[i] = z;
        ((float4*)g_gsum)[i]  = z;
        if (i < NE * COUT / 4) ((float4*)g_esum)[i] = z;
        if (i < NE)            g_ecnt[i] = 0.f;
        if (i < NV) { g_vcnt_hg[i] = 0.f; g_vcnt_g[i] = 0.f; }
    }
}

// ---------------- fused MLP: h = lrelu(x@W1+b1)@W2 + b2 --------------------
// f32x2 packed FMA, K-paired accumulators (lo=even-k, hi=odd-k partial sums).
// Weights transposed in smem with +2 row padding -> conflict-free 64-bit LDS.
#define TILE_R 32
#define RPW    4
#define MLP_THREADS 256
#define S1 (CIN + 2)    // 258: W1T row stride (floats)
#define S2 (CMID + 2)   // 130: W2T row stride
#define SMEM_FLOATS (CMID*S1 + COUT*S2 + TILE_R*CIN + TILE_R*CMID + CMID + COUT)

__global__ __launch_bounds__(MLP_THREADS, 1)
void mlp_kernel(const float* __restrict__ x,
                const float* __restrict__ W1, const float* __restrict__ b1,
                const float* __restrict__ W2, const float* __restrict__ b2) {
    extern __shared__ float sm[];
    float* W1T  = sm;                        // [128][258]  (W1T[j][k] = W1[k][j])
    float* W2T  = W1T + CMID * S1;           // [64][130]
    float* xs   = W2T + COUT * S2;           // [32][256]
    float* mids = xs  + TILE_R * CIN;        // [32][128]
    float* b1s  = mids + TILE_R * CMID;      // [128]
    float* b2s  = b1s + CMID;                // [64]

    int tid = threadIdx.x;
    // transpose W1 into smem (one-time per block)
    for (int i = tid; i < CIN * CMID; i += MLP_THREADS) {
        int k = i >> 7, j = i & 127;         // W1[k][j]
        W1T[j * S1 + k] = W1[i];
    }
    for (int i = tid; i < CMID * COUT; i += MLP_THREADS) {
        int k = i >> 6, j = i & 63;          // W2[k][j]
        W2T[j * S2 + k] = W2[i];
    }
    if (tid < CMID) b1s[tid] = b1[tid];
    if (tid < COUT) b2s[tid] = b2[tid];

    int warp = tid >> 5, lane = tid & 31;
    int ntiles = NV / TILE_R;   // 3125, exact

    for (int tile = blockIdx.x; tile < ntiles; tile += gridDim.x) {
        __syncthreads();
        int row0 = tile * TILE_R;
        for (int i = tid; i < TILE_R * CIN / 4; i += MLP_THREADS)
            ((float4*)xs)[i] = ((const float4*)(x + (size_t)row0 * CIN))[i];
        __syncthreads();

        // ---- GEMM1: rows warp*RPW.., cols j = jj*32+lane (jj=0..3) --------
        u64 acc[RPW][4];
#pragma unroll
        for (int r = 0; r < RPW; r++)
#pragma unroll
            for (int jj = 0; jj < 4; jj++) acc[r][jj] = 0ull;

        const float* xrow = xs + (warp * RPW) * CIN;
        const float* wbase = W1T + lane * S1;
#pragma unroll 4
        for (int k = 0; k < CIN; k += 2) {
            u64 xv[RPW], wv[4];
#pragma unroll
            for (int r = 0; r < RPW; r++)
                xv[r] = *(const u64*)(xrow + r * CIN + k);
#pragma unroll
            for (int jj = 0; jj < 4; jj++)
                wv[jj] = *(const u64*)(wbase + (jj * 32) * S1 + k);
#pragma unroll
            for (int r = 0; r < RPW; r++)
#pragma unroll
                for (int jj = 0; jj < 4; jj++)
                    acc[r][jj] = fma2(xv[r], wv[jj], acc[r][jj]);
        }
        // bias + leaky relu -> mids
#pragma unroll
        for (int jj = 0; jj < 4; jj++) {
            int j = jj * 32 + lane;
            float b = b1s[j];
#pragma unroll
            for (int r = 0; r < RPW; r++)
                mids[(warp * RPW + r) * CMID + j] = lrelu(sum2(acc[r][jj]) + b);
        }
        __syncwarp();

        // ---- GEMM2: cols j = jj*32+lane (jj=0..1) -------------------------
        u64 acc2[RPW][2];
#pragma unroll
        for (int r = 0; r < RPW; r++) { acc2[r][0] = 0ull; acc2[r][1] = 0ull; }

        const float* mrow = mids + (warp * RPW) * CMID;
        const float* w2base = W2T + lane * S2;
#pragma unroll 4
        for (int k = 0; k < CMID; k += 2) {
            u64 mv[RPW], wv[2];
#pragma unroll
            for (int r = 0; r < RPW; r++)
                mv[r] = *(const u64*)(mrow + r * CMID + k);
#pragma unroll
            for (int jj = 0; jj < 2; jj++)
                wv[jj] = *(const u64*)(w2base + (jj * 32) * S2 + k);
#pragma unroll
            for (int r = 0; r < RPW; r++)
#pragma unroll
                for (int jj = 0; jj < 2; jj++)
                    acc2[r][jj] = fma2(mv[r], wv[jj], acc2[r][jj]);
        }
#pragma unroll
        for (int jj = 0; jj < 2; jj++) {
            int j = jj * 32 + lane;
            float b = b2s[j];
#pragma unroll
            for (int r = 0; r < RPW; r++)
                g_h[(size_t)(row0 + warp * RPW + r) * COUT + j] = sum2(acc2[r][jj]) + b;
        }
    }
}

// ---------------- scatter-add (mean numerator + count) ---------------------
__global__ void scatter_kernel(const float* __restrict__ feat,
                               const int* __restrict__ sidx,
                               const int* __restrict__ didx,
                               float* __restrict__ sum,
                               float* __restrict__ cnt,
                               int npairs) {
    int t = blockIdx.x * blockDim.x + threadIdx.x;
    int i = t >> 4;
    if (i >= npairs) return;
    int l = t & 15;
    int s = __ldg(sidx + i);
    int d = __ldg(didx + i);
    float4 v = *(const float4*)(feat + (size_t)s * COUT + l * 4);
    float* dst = sum + (size_t)d * COUT + l * 4;
    asm volatile("red.global.add.v4.f32 [%0], {%1,%2,%3,%4};"
                 :: "l"(dst), "f"(v.x), "f"(v.y), "f"(v.z), "f"(v.w)
                 : "memory");
    if (l == 0) atomicAdd(cnt + d, 1.0f);
}

// ---------------- e_feat = e_sum / max(cnt,1) -------------------------------
__global__ void efeat_kernel() {
    int i = blockIdx.x * blockDim.x + threadIdx.x;
    if (i >= NE * COUT) return;
    float c = g_ecnt[i >> 6];
    g_efeat[i] = g_esum[i] / fmaxf(c, 1.0f);
}

// ---------------- final fuse + activation ----------------------------------
__global__ void final_kernel(const float* __restrict__ w, float* __restrict__ out) {
    int t = blockIdx.x * blockDim.x + threadIdx.x;
    if (t >= NV * COUT / 4) return;
    int v = t >> 4;
    float e0 = expf(w[0]), e1 = expf(w[1]);
    float sw0 = e0 / (e0 + e1), sw1 = e1 / (e0 + e1);
    float ih = 1.0f / fmaxf(g_vcnt_hg[v], 1.0f);
    float ig = 1.0f / fmaxf(g_vcnt_g[v], 1.0f);
    float4 hg = ((const float4*)g_hgsum)[t];
    float4 gg = ((const float4*)g_gsum)[t];
    float4 h  = ((const float4*)g_h)[t];
    float4 o;
    o.x = lrelu(sw0 * 0.5f * (gg.x * ig + hg.x * ih) + sw1 * h.x);
    o.y = lrelu(sw0 * 0.5f * (gg.y * ig + hg.y * ih) + sw1 * h.y);
    o.z = lrelu(sw0 * 0.5f * (gg.z * ig + hg.z * ih) + sw1 * h.z);
    o.w = lrelu(sw0 * 0.5f * (gg.w * ig + hg.w * ih) + sw1 * h.w);
    ((float4*)out)[t] = o;
}

// ---------------- launch ----------------------------------------------------
extern "C" void kernel_launch(void* const* d_in, const int* in_sizes, int n_in,
                              void* d_out, int out_size) {
    const float* x    = (const float*)d_in[0];
    const float* W1   = (const float*)d_in[1];
    const float* b1   = (const float*)d_in[2];
    const float* W2   = (const float*)d_in[3];
    const float* b2   = (const float*)d_in[4];
    const float* w    = (const float*)d_in[5];
    const int*   hg_v = (const int*)d_in[6];
    const int*   hg_e = (const int*)d_in[7];
    const int*   g_src= (const int*)d_in[8];
    const int*   g_dst= (const int*)d_in[9];
    float* out = (float*)d_out;

    float *p_h, *p_esum, *p_ecnt, *p_efeat, *p_hgsum, *p_gsum, *p_vch, *p_vcg;
    cudaGetSymbolAddress((void**)&p_h,     g_h);
    cudaGetSymbolAddress((void**)&p_esum,  g_esum);
    cudaGetSymbolAddress((void**)&p_ecnt,  g_ecnt);
    cudaGetSymbolAddress((void**)&p_efeat, g_efeat);
    cudaGetSymbolAddress((void**)&p_hgsum, g_hgsum);
    cudaGetSymbolAddress((void**)&p_gsum,  g_gsum);
    cudaGetSymbolAddress((void**)&p_vch,   g_vcnt_hg);
    cudaGetSymbolAddress((void**)&p_vcg,   g_vcnt_g);

    const size_t smem_bytes = (size_t)SMEM_FLOATS * sizeof(float); // ~210KB
    cudaFuncSetAttribute(mlp_kernel, cudaFuncAttributeMaxDynamicSharedMemorySize,
                         (int)smem_bytes);

    zero_kernel<<<2048, 256>>>();
    mlp_kernel<<<148, MLP_THREADS, smem_bytes>>>(x, W1, b1, W2, b2);

    int sc_blocks = (NP * 16 + 255) / 256;
    // v2e: mean of h over incidence pairs grouped by hyperedge
    scatter_kernel<<<sc_blocks, 256>>>(p_h, hg_v, hg_e, p_esum, p_ecnt, NP);
    efeat_kernel<<<(NE * COUT + 255) / 256, 256>>>();
    // e2v: mean of e_feat over incidence pairs grouped by vertex
    scatter_kernel<<<sc_blocks, 256>>>(p_efeat, hg_e, hg_v, p_hgsum, p_vch, NP);
    // graph: mean of h over edges grouped by destination vertex
    scatter_kernel<<<sc_blocks, 256>>>(p_h, g_src, g_dst, p_gsum, p_vcg, NP);

    final_kernel<<<(NV * COUT / 4 + 255) / 256, 256>>>(w, out);
}